// round 4
// baseline (speedup 1.0000x reference)
#include <cuda_runtime.h>

// YoloLayer2: x (16, 3*85, 76, 76) f32 -> out (16, 3, 76, 76, 85) f32
// Persistent software-pipelined transpose+activation.

#define NUM_B 16
#define NUM_A 3
#define DIM_H 76
#define DIM_W 76
#define HW (DIM_H * DIM_W)        // 5776
#define ATTR 85
#define TILE_P 64                 // pixels per tile (smem = 64*85*4 = 21760 B)
#define V4 (TILE_P / 4)           // 16 float4 per attr row
#define NTHREADS 256
#define ITEMS (ATTR * V4)         // 1360 float4 work items per tile
#define NITER 6                   // ceil(ITEMS / NTHREADS)
#define TILES_PER_BA 91           // ceil(5776/64), last tile has 16 pixels
#define TILES_TOTAL (NUM_B * NUM_A * TILES_PER_BA)   // 4368
#define NBLOCKS (148 * 6)         // one resident wave, persistent

// sigmoid(v) = 0.5*tanh(v/2) + 0.5  -- single MUFU + FMA
__device__ __forceinline__ float fsigmoid(float v) {
    float t;
    asm("tanh.approx.f32 %0, %1;" : "=f"(t) : "f"(v * 0.5f));
    return fmaf(t, 0.5f, 0.5f);
}

__global__ __launch_bounds__(NTHREADS, 6)
void yolo_kernel(const float* __restrict__ x, float* __restrict__ out) {
    __shared__ float sm[TILE_P * ATTR];   // 21760 bytes

    const int tid = threadIdx.x;
    const int G   = gridDim.x;

    // Per-thread static item decomposition: item i -> idx = tid + i*256
    // attr = idx/16, pl = (idx%16)*4
    int attr_i[NITER], pl_i[NITER];
    bool item_ok[NITER];
    #pragma unroll
    for (int i = 0; i < NITER; i++) {
        int idx = tid + i * NTHREADS;
        attr_i[i] = idx >> 4;
        pl_i[i]   = (idx & 15) << 2;
        item_ok[i] = (idx < ITEMS);
    }

    float4 v[NITER];

    // ---- prefetch first tile ----
    int t = blockIdx.x;
    {
        const int ba      = t / TILES_PER_BA;
        const int tile_in = t - ba * TILES_PER_BA;
        const int p0      = tile_in * TILE_P;
        const int nvalid  = min(TILE_P, HW - p0);
        const float* bin  = x + (size_t)ba * ATTR * HW + p0;
        #pragma unroll
        for (int i = 0; i < NITER; i++)
            if (item_ok[i] && pl_i[i] < nvalid)
                v[i] = *(const float4*)(bin + attr_i[i] * HW + pl_i[i]);
    }

    for (; t < TILES_TOTAL; t += G) {
        const int ba      = t / TILES_PER_BA;
        const int tile_in = t - ba * TILES_PER_BA;
        const int a       = ba % NUM_A;
        const int p0      = tile_in * TILE_P;
        const int nvalid  = min(TILE_P, HW - p0);

        const float AW[3] = {10.0f, 13.0f, 16.0f};
        const float AH[3] = {13.0f, 16.0f, 30.0f};
        const float sw = AW[a] * (1.0f / 608.0f);
        const float sh = AH[a] * (1.0f / 608.0f);

        // next tile pointers (for prefetch interleaved with compute)
        const int tn = t + G;
        const float* binn = nullptr;
        int nvalid_n = 0;
        if (tn < TILES_TOTAL) {
            const int ban = tn / TILES_PER_BA;
            const int tin = tn - ban * TILES_PER_BA;
            const int p0n = tin * TILE_P;
            nvalid_n = min(TILE_P, HW - p0n);
            binn = x + (size_t)ban * ATTR * HW + p0n;
        }

        // ---- compute + STS tile t; issue prefetch of tile t+G as each
        //      v[i] is consumed ----
        #pragma unroll
        for (int i = 0; i < NITER; i++) {
            const int attr = attr_i[i];
            const int pl   = pl_i[i];
            if (item_ok[i] && pl < nvalid) {
                float vv[4] = {v[i].x, v[i].y, v[i].z, v[i].w};
                float r[4];
                if (attr >= 4) {
                    #pragma unroll
                    for (int k = 0; k < 4; k++) r[k] = fsigmoid(vv[k]);
                } else if (attr == 0) {
                    #pragma unroll
                    for (int k = 0; k < 4; k++) {
                        const int p  = p0 + pl + k;
                        const int wi = p % DIM_W;
                        r[k] = ((float)wi + fsigmoid(vv[k])) * (1.0f / 76.0f);
                    }
                } else if (attr == 1) {
                    #pragma unroll
                    for (int k = 0; k < 4; k++) {
                        const int p  = p0 + pl + k;
                        const int hj = p / DIM_W;
                        r[k] = ((float)hj + fsigmoid(vv[k])) * (1.0f / 76.0f);
                    }
                } else if (attr == 2) {
                    #pragma unroll
                    for (int k = 0; k < 4; k++) r[k] = __expf(vv[k]) * sw;
                } else { // attr == 3
                    #pragma unroll
                    for (int k = 0; k < 4; k++) r[k] = __expf(vv[k]) * sh;
                }
                float* row = sm + pl * ATTR + attr;
                #pragma unroll
                for (int k = 0; k < 4; k++) row[k * ATTR] = r[k];
            }
            // prefetch same item for next tile (independent of compute above)
            if (binn && item_ok[i] && pl < nvalid_n)
                v[i] = *(const float4*)(binn + attr * HW + pl);
        }
        __syncthreads();

        // ---- stream smem -> gmem (contiguous, float4-coalesced) while the
        //      prefetch LDGs for tile t+G are in flight ----
        {
            float* base_out = out + (size_t)(ba * HW + p0) * ATTR;
            const int total4 = (nvalid * ATTR) >> 2;
            const float4* s4 = (const float4*)sm;
            float4* o4 = (float4*)base_out;
            for (int k = tid; k < total4; k += NTHREADS)
                o4[k] = s4[k];
        }
        __syncthreads();   // protect smem reuse before next tile's STS
    }
}

extern "C" void kernel_launch(void* const* d_in, const int* in_sizes, int n_in,
                              void* d_out, int out_size) {
    const float* x = (const float*)d_in[0];
    float* out = (float*)d_out;
    yolo_kernel<<<NBLOCKS, NTHREADS>>>(x, out);
}